// round 6
// baseline (speedup 1.0000x reference)
#include <cuda_runtime.h>
#include <cuda_fp16.h>
#include <cstdint>

// ---------------- Problem constants ----------------
#define B_SZ     4
#define L_SZ     4096
#define DIM      768
#define D_STATE  16
#define D_CONV   4
#define D_INNER  1536
#define DT_RANK  48
#define E2       (2*D_INNER) // 3072
#define NTOK     (B_SZ*L_SZ) // 16384
#define XDBL_C   (DT_RANK + 2*D_STATE) // 80

// ---------------- Scratch ----------------
__device__ float g_xz  [(size_t)NTOK * E2];
__device__ float g_dt  [2 * (size_t)NTOK * D_INNER];
__device__ float g_xdbl[2 * (size_t)NTOK * XDBL_C];
__device__ float g_y   [2 * (size_t)NTOK * D_INNER];

__device__ __align__(16) __half s_xh [(size_t)NTOK * DIM];
__device__ __align__(16) __half s_xl [(size_t)NTOK * DIM];
__device__ __align__(16) __half s_wi [(size_t)E2 * DIM];
__device__ __align__(16) __half s_wo [(size_t)DIM * D_INNER];
__device__ __align__(16) __half s_wx [2 * (size_t)XDBL_C * D_INNER];
__device__ __align__(16) __half s_wd [2 * (size_t)D_INNER * DT_RANK];
__device__ __align__(16) __half s_xch[2 * (size_t)NTOK * D_INNER];
__device__ __align__(16) __half s_xcl[2 * (size_t)NTOK * D_INNER];
__device__ __align__(16) __half s_dtrh[2 * (size_t)NTOK * DT_RANK];
__device__ __align__(16) __half s_dtrl[2 * (size_t)NTOK * DT_RANK];
__device__ __align__(16) __half s_ysh[(size_t)NTOK * D_INNER];
__device__ __align__(16) __half s_ysl[(size_t)NTOK * D_INNER];

// ---------------- helpers ----------------
__device__ __forceinline__ float softplusf(float x) {
    return (x > 20.f) ? x : log1pf(__expf(x));
}
__device__ __forceinline__ float siluf(float x) {
    return x / (1.f + __expf(-x));
}
__device__ __forceinline__ uint32_t smem_u32(const void* p) {
    uint32_t a;
    asm("{ .reg .u64 t; cvta.to.shared.u64 t, %1; cvt.u32.u64 %0, t; }" : "=r"(a) : "l"(p));
    return a;
}
__device__ __forceinline__ void ldsm4(uint32_t* r, uint32_t addr) {
    asm volatile("ldmatrix.sync.aligned.m8n8.x4.shared.b16 {%0,%1,%2,%3}, [%4];"
        : "=r"(r[0]), "=r"(r[1]), "=r"(r[2]), "=r"(r[3]) : "r"(addr));
}
__device__ __forceinline__ void mma_f16(float* c, const uint32_t* a, const uint32_t* b) {
    asm volatile("mma.sync.aligned.m16n8k16.row.col.f32.f16.f16.f32 "
        "{%0,%1,%2,%3}, {%4,%5,%6,%7}, {%8,%9}, {%0,%1,%2,%3};"
        : "+f"(c[0]), "+f"(c[1]), "+f"(c[2]), "+f"(c[3])
        : "r"(a[0]), "r"(a[1]), "r"(a[2]), "r"(a[3]), "r"(b[0]), "r"(b[1]));
}
__device__ __forceinline__ void cp16(uint32_t dst, const void* src, bool pred) {
    const int sz = pred ? 16 : 0;
    asm volatile("cp.async.cg.shared.global [%0], [%1], 16, %2;"
        :: "r"(dst), "l"(src), "r"(sz) : "memory");
}
__device__ __forceinline__ void split2h(float v, __half& h, __half& l) {
    h = __float2half_rn(v);
    l = __float2half_rn(v - __half2float(h));
}

// ---------------- conversion kernels ----------------
__global__ void cvt_split(const float* __restrict__ src,
                          __half* __restrict__ h, __half* __restrict__ l, int n4)
{
    for (int i = blockIdx.x * blockDim.x + threadIdx.x; i < n4; i += gridDim.x * blockDim.x) {
        float4 v = ((const float4*)src)[i];
        __half h0,h1,h2,h3,l0,l1,l2,l3;
        split2h(v.x,h0,l0); split2h(v.y,h1,l1); split2h(v.z,h2,l2); split2h(v.w,h3,l3);
        __half2 hh01{h0,h1}, hh23{h2,h3}, ll01{l0,l1}, ll23{l2,l3};
        ((uint2*)h)[i] = make_uint2(*(uint32_t*)&hh01, *(uint32_t*)&hh23);
        ((uint2*)l)[i] = make_uint2(*(uint32_t*)&ll01, *(uint32_t*)&ll23);
    }
}

__global__ void cvt_h(const float* __restrict__ src, __half* __restrict__ h, int n4)
{
    for (int i = blockIdx.x * blockDim.x + threadIdx.x; i < n4; i += gridDim.x * blockDim.x) {
        float4 v = ((const float4*)src)[i];
        __half2 a{__float2half_rn(v.x), __float2half_rn(v.y)};
        __half2 b{__float2half_rn(v.z), __float2half_rn(v.w)};
        ((uint2*)h)[i] = make_uint2(*(uint32_t*)&a, *(uint32_t*)&b);
    }
}

__global__ void cvt_h2(const float* __restrict__ s0, __half* __restrict__ d0,
                       const float* __restrict__ s1, __half* __restrict__ d1, int n4)
{
    const float* src = blockIdx.y ? s1 : s0;
    __half* h = blockIdx.y ? d1 : d0;
    for (int i = blockIdx.x * blockDim.x + threadIdx.x; i < n4; i += gridDim.x * blockDim.x) {
        float4 v = ((const float4*)src)[i];
        __half2 a{__float2half_rn(v.x), __float2half_rn(v.y)};
        __half2 b{__float2half_rn(v.z), __float2half_rn(v.w)};
        ((uint2*)h)[i] = make_uint2(*(uint32_t*)&a, *(uint32_t*)&b);
    }
}

__global__ void cvt_add_split(const float* __restrict__ a, const float* __restrict__ b,
                              __half* __restrict__ h, __half* __restrict__ l, int n4)
{
    for (int i = blockIdx.x * blockDim.x + threadIdx.x; i < n4; i += gridDim.x * blockDim.x) {
        float4 va = ((const float4*)a)[i];
        float4 vb = ((const float4*)b)[i];
        va.x += vb.x; va.y += vb.y; va.z += vb.z; va.w += vb.w;
        __half h0,h1,h2,h3,l0,l1,l2,l3;
        split2h(va.x,h0,l0); split2h(va.y,h1,l1); split2h(va.z,h2,l2); split2h(va.w,h3,l3);
        __half2 hh01{h0,h1}, hh23{h2,h3}, ll01{l0,l1}, ll23{l2,l3};
        ((uint2*)h)[i] = make_uint2(*(uint32_t*)&hh01, *(uint32_t*)&hh23);
        ((uint2*)l)[i] = make_uint2(*(uint32_t*)&ll01, *(uint32_t*)&ll23);
    }
}

// ---------------- 128x256 2-pass fp16-split HMMA GEMM, 4-stage cp.async ----------------
#define BM 128
#define BN 256
#define BKC 32
#define PAD 40           // halves per smem row (80B)
#define OFF_AH 0
#define OFF_AL 10240
#define OFF_B  20480
#define STAGE_B 40960
#define NSTAGE 4

struct GArg {
    const __half *Ah, *Al, *Bh;
    const float* bias;
    float* C;
    __half *Dh, *Dl;
};

__global__ __launch_bounds__(512, 1) void gemm_sp(
    GArg g0, GArg g1, int lda, int ldb, int ldc, int M, int N, int K, int epi)
{
    extern __shared__ char smem[];
    const uint32_t sbase = smem_u32(smem);
    const GArg g = (blockIdx.z == 0) ? g0 : g1;

    const int tid  = threadIdx.x;
    const int lane = tid & 31;
    const int wid  = tid >> 5;         // 0..15
    const int warpM = wid & 3;         // 4 M-warps (32 rows)
    const int warpN = wid >> 2;        // 4 N-warps (64 cols)

    // group-of-8 M rasterization (gridDim.y % 8 == 0)
    int bmb, bnb;
    {
        const int nbn = gridDim.x;
        const int bid = blockIdx.y * nbn + blockIdx.x;
        const int per = 8 * nbn;
        const int grp = bid / per;
        const int r   = bid % per;
        bmb = grp * 8 + (r % 8);
        bnb = r / 8;
    }
    const int bm = bmb * BM;
    const int bn = bnb * BN;

    float acc[2][8][4];
    #pragma unroll
    for (int f = 0; f < 2; f++)
        #pragma unroll
        for (int gg = 0; gg < 8; gg++)
            #pragma unroll
            for (int i = 0; i < 4; i++) acc[f][gg][i] = 0.f;

    const int aRow = warpM * 32 + (lane & 15);
    const int aCol = (lane >> 4) * 8;
    const int bRow = warpN * 64 + (lane & 7) + ((lane >> 4) & 1) * 8;
    const int bCol = ((lane >> 3) & 1) * 8;

    const int nch = (K + BKC - 1) / BKC;

    auto issue = [&](int c) {
        if (c < nch) {
            const int k0 = c * BKC;
            const uint32_t st = sbase + (c % NSTAGE) * STAGE_B;
            const int r   = tid >> 2;        // 0..127
            const int c16 = tid & 3;
            const int kk  = k0 + c16 * 8;
            const bool vK = kk < K;
            const size_t ao = vK ? ((size_t)(bm + r) * lda + kk) : 0;
            const uint32_t soA = (uint32_t)(r * (PAD * 2) + c16 * 16);
            cp16(st + OFF_AH + soA, g.Ah + ao, vK);
            cp16(st + OFF_AL + soA, g.Al + ao, vK);
            #pragma unroll
            for (int it = 0; it < 2; it++) {
                const int row = r + 128 * it;
                const bool vB = vK && ((bn + row) < N);
                const size_t bo = vB ? ((size_t)(bn + row) * ldb + kk) : 0;
                cp16(st + OFF_B + (uint32_t)(row * (PAD * 2) + c16 * 16), g.Bh + bo, vB);
            }
        }
        asm volatile("cp.async.commit_group;" ::: "memory");
    };

    issue(0); issue(1); issue(2);

    for (int c = 0; c < nch; c++) {
        asm volatile("cp.async.wait_group 2;" ::: "memory");
        __syncthreads();

        const uint32_t st = sbase + (c % NSTAGE) * STAGE_B;
        #pragma unroll
        for (int ks = 0; ks < 2; ks++) {
            const int kc = ks * 16;
            uint32_t bfr[8][2], afr[2][4];
            #pragma unroll
            for (int p = 0; p < 4; p++) {
                uint32_t r4[4];
                ldsm4(r4, st + OFF_B + (uint32_t)((bRow + p*16) * PAD + kc + bCol) * 2);
                bfr[2*p][0] = r4[0]; bfr[2*p][1] = r4[1];
                bfr[2*p+1][0] = r4[2]; bfr[2*p+1][1] = r4[3];
            }
            #pragma unroll
            for (int f = 0; f < 2; f++)
                ldsm4(afr[f], st + OFF_AH + (uint32_t)((aRow + f*16) * PAD + kc + aCol) * 2);
            #pragma unroll
            for (int f = 0; f < 2; f++)
                #pragma unroll
                for (int gg = 0; gg < 8; gg++) mma_f16(acc[f][gg], afr[f], bfr[gg]);
            #pragma unroll
            for (int f = 0; f < 2; f++)
                ldsm4(afr[f], st + OFF_AL + (uint32_t)((aRow + f*16) * PAD + kc + aCol) * 2);
            #pragma unroll
            for (int f = 0; f < 2; f++)
                #pragma unroll
                for (int gg = 0; gg < 8; gg++) mma_f16(acc[f][gg], afr[f], bfr[gg]);
        }
        __syncthreads();
        issue(c + 3);
    }

    // epilogue
    #pragma unroll
    for (int f = 0; f < 2; f++) {
        const int r0 = bm + warpM * 32 + f * 16 + (lane >> 2);
        #pragma unroll
        for (int gg = 0; gg < 8; gg++) {
            const int col = bn + warpN * 64 + gg * 8 + 2 * (lane & 3);
            if (col < N) {
                float v0 = acc[f][gg][0], v1 = acc[f][gg][1];
                float v2 = acc[f][gg][2], v3 = acc[f][gg][3];
                if (g.bias) {
                    const float b0 = g.bias[col], b1 = g.bias[col + 1];
                    v0 += b0; v1 += b1; v2 += b0; v3 += b1;
                }
                if (epi == 1) {
                    v0 = softplusf(v0); v1 = softplusf(v1);
                    v2 = softplusf(v2); v3 = softplusf(v3);
                }
                *(float2*)(g.C + (size_t)r0 * ldc + col)       = make_float2(v0, v1);
                *(float2*)(g.C + (size_t)(r0 + 8) * ldc + col) = make_float2(v2, v3);
                if (epi == 2 && col < DT_RANK) {
                    __half h0,l0,h1,l1,h2,l2,h3,l3;
                    split2h(v0,h0,l0); split2h(v1,h1,l1);
                    split2h(v2,h2,l2); split2h(v3,h3,l3);
                    __half2 ha{h0,h1}, la{l0,l1}, hb{h2,h3}, lb{l2,l3};
                    *(__half2*)(g.Dh + (size_t)r0 * DT_RANK + col)       = ha;
                    *(__half2*)(g.Dl + (size_t)r0 * DT_RANK + col)       = la;
                    *(__half2*)(g.Dh + (size_t)(r0 + 8) * DT_RANK + col) = hb;
                    *(__half2*)(g.Dl + (size_t)(r0 + 8) * DT_RANK + col) = lb;
                }
            }
        }
    }
}

// ---------------- Causal depthwise conv (k=4) + SiLU -> split fp16 ----------------
__global__ void conv_silu_kernel(
    const float* __restrict__ wf, const float* __restrict__ bf,
    const float* __restrict__ wb, const float* __restrict__ bb)
{
    const int dir = blockIdx.y;
    const size_t idx = (size_t)blockIdx.x * blockDim.x + threadIdx.x;
    if (idx >= (size_t)NTOK * D_INNER) return;
    const int d = (int)(idx % D_INNER);
    const size_t bl = idx / D_INNER;
    const int l = (int)(bl % L_SZ);
    const int b = (int)(bl / L_SZ);

    const float* w = dir ? wb : wf;
    float acc = dir ? bb[d] : bf[d];
    #pragma unroll
    for (int j = 0; j < D_CONV; j++) {
        const int m = l - (D_CONV - 1) + j;
        if (m >= 0) {
            const int src = dir ? (L_SZ - 1 - m) : m;
            acc += w[d * D_CONV + j] * g_xz[((size_t)b * L_SZ + src) * E2 + d];
        }
    }
    const float v = siluf(acc);
    __half h, lo;
    split2h(v, h, lo);
    const size_t o = ((size_t)dir * NTOK + bl) * D_INNER + d;
    s_xch[o] = h;
    s_xcl[o] = lo;
}

// ---------------- Selective scan ----------------
#define SCHUNK 64
__global__ __launch_bounds__(128) void scan_kernel(
    const float* __restrict__ A_log_f, const float* __restrict__ D_f,
    const float* __restrict__ A_log_b, const float* __restrict__ D_b)
{
    const int dir = blockIdx.z;
    const int b   = blockIdx.y;
    const int d   = blockIdx.x * blockDim.x + threadIdx.x;
    const int tid = threadIdx.x;

    const size_t dirTok = (size_t)dir * NTOK;
    const __half* xch = s_xch + dirTok * D_INNER;
    const __half* xcl = s_xcl + dirTok * D_INNER;
    const float* dtp  = g_dt   + dirTok * D_INNER;
    const float* xdbl = g_xdbl + dirTok * XDBL_C;
    float*       yout = g_y    + dirTok * D_INNER;
    const float* Alog = dir ? A_log_b : A_log_f;
    const float* Dv   = dir ? D_b     : D_f;

    float A[D_STATE];
    #pragma unroll
    for (int n = 0; n < D_STATE; n++) A[n] = -__expf(Alog[d * D_STATE + n]);
    const float Dd = Dv[d];

    float h[D_STATE];
    #pragma unroll
    for (int n = 0; n < D_STATE; n++) h[n] = 0.f;

    __shared__ float sBC[SCHUNK][2 * D_STATE];

    for (int l0 = 0; l0 < L_SZ; l0 += SCHUNK) {
        __syncthreads();
        for (int i = tid; i < SCHUNK * 2 * D_STATE; i += blockDim.x) {
            const int t = i >> 5, c = i & 31;
            sBC[t][c] = xdbl[((size_t)b * L_SZ + l0 + t) * XDBL_C + DT_RANK + c];
        }
        __syncthreads();

        for (int t = 0; t < SCHUNK; t++) {
            const int l = l0 + t;
            const size_t base = ((size_t)b * L_SZ + l) * D_INNER + d;
            const float u   = __half2float(xch[base]) + __half2float(xcl[base]);
            const float dtv = dtp[base];
            const float dtu = dtv * u;
            float y = 0.f;
            #pragma unroll
            for (int n = 0; n < D_STATE; n++) {
                const float dA = __expf(dtv * A[n]);
                h[n] = h[n] * dA + dtu * sBC[t][n];
                y += h[n] * sBC[t][D_STATE + n];
            }
            y += u * Dd;
            const int lsrc = dir ? (L_SZ - 1 - l) : l;
            const float zv = g_xz[((size_t)b * L_SZ + lsrc) * E2 + D_INNER + d];
            yout[((size_t)b * L_SZ + lsrc) * D_INNER + d] = y * siluf(zv);
        }
    }
}

// ---------------- Launch ----------------
extern "C" void kernel_launch(void* const* d_in, const int* in_sizes, int n_in,
                              void* d_out, int out_size)
{
    const float* x            = (const float*)d_in[0];
    const float* in_proj_w    = (const float*)d_in[1];
    const float* out_proj_w   = (const float*)d_in[2];
    const float* conv1d_w     = (const float*)d_in[3];
    const float* conv1d_bias  = (const float*)d_in[4];
    const float* x_proj_w     = (const float*)d_in[5];
    const float* dt_proj_w    = (const float*)d_in[6];
    const float* dt_proj_bias = (const float*)d_in[7];
    const float* A_log        = (const float*)d_in[8];
    const float* Dvec         = (const float*)d_in[9];
    const float* conv1d_w_b   = (const float*)d_in[10];
    const float* conv1d_bias_b= (const float*)d_in[11];
    const float* x_proj_w_b   = (const float*)d_in[12];
    const float* dt_proj_w_b  = (const float*)d_in[13];
    const float* dt_proj_bias_b=(const float*)d_in[14];
    const float* A_log_b      = (const float*)d_in[15];
    const float* D_b          = (const float*)d_in[16];
    float* out = (float*)d_out;

    float *p_xz, *p_dt, *p_xdbl, *p_y;
    __half *p_xh,*p_xl,*p_wi,*p_wo,*p_wx,*p_wd,*p_xch,*p_xcl,*p_dtrh,*p_dtrl,*p_ysh,*p_ysl;
    cudaGetSymbolAddress((void**)&p_xz,   g_xz);
    cudaGetSymbolAddress((void**)&p_dt,   g_dt);
    cudaGetSymbolAddress((void**)&p_xdbl, g_xdbl);
    cudaGetSymbolAddress((void**)&p_y,    g_y);
    cudaGetSymbolAddress((void**)&p_xh,  s_xh);   cudaGetSymbolAddress((void**)&p_xl,  s_xl);
    cudaGetSymbolAddress((void**)&p_wi,  s_wi);
    cudaGetSymbolAddress((void**)&p_wo,  s_wo);
    cudaGetSymbolAddress((void**)&p_wx,  s_wx);
    cudaGetSymbolAddress((void**)&p_wd,  s_wd);
    cudaGetSymbolAddress((void**)&p_xch, s_xch);  cudaGetSymbolAddress((void**)&p_xcl, s_xcl);
    cudaGetSymbolAddress((void**)&p_dtrh,s_dtrh); cudaGetSymbolAddress((void**)&p_dtrl,s_dtrl);
    cudaGetSymbolAddress((void**)&p_ysh, s_ysh);  cudaGetSymbolAddress((void**)&p_ysl, s_ysl);

    cudaFuncSetAttribute(gemm_sp, cudaFuncAttributeMaxDynamicSharedMemorySize, NSTAGE * STAGE_B);

    const size_t tokDI = (size_t)NTOK * D_INNER;
    const size_t tokXD = (size_t)NTOK * XDBL_C;
    const size_t wx1   = (size_t)XDBL_C * D_INNER;
    const size_t wd1   = (size_t)D_INNER * DT_RANK;
    const size_t dtr1  = (size_t)NTOK * DT_RANK;

    // launches 1-2: prerequisites for in_proj
    cvt_split<<<2048, 256>>>(x, p_xh, p_xl, NTOK * DIM / 4);
    cvt_h<<<1024, 256>>>(in_proj_w, p_wi, E2 * DIM / 4);

    // launches 3-6: in_proj in 4 N-slices (ncu -s 5 -c 1 lands on one of these)
    for (int s = 0; s < 4; s++) {
        GArg a{p_xh, p_xl, p_wi + (size_t)s * 768 * DIM, nullptr,
               p_xz + (size_t)s * 768, nullptr, nullptr};
        dim3 grid(768 / BN, NTOK / BM, 1);
        gemm_sp<<<grid, 512, NSTAGE*STAGE_B>>>(a, a, DIM, DIM, E2, NTOK, 768, DIM, 0);
    }

    // remaining weight conversions
    cvt_h<<< 512, 256>>>(out_proj_w, p_wo, DIM * D_INNER / 4);
    cvt_h2<<<dim3(128, 2), 256>>>(x_proj_w, p_wx, x_proj_w_b, p_wx + wx1, (int)(wx1 / 4));
    cvt_h2<<<dim3(128, 2), 256>>>(dt_proj_w, p_wd, dt_proj_w_b, p_wd + wd1, (int)(wd1 / 4));

    // conv + silu -> split fp16
    {
        dim3 grid((unsigned)(((size_t)NTOK * D_INNER + 255) / 256), 2);
        conv_silu_kernel<<<grid, 256>>>(conv1d_w, conv1d_bias, conv1d_w_b, conv1d_bias_b);
    }

    // x_proj both dirs (16384 x 80, K=1536), epilogue splits dt_r
    {
        GArg a0{p_xch,         p_xcl,         p_wx,       nullptr, p_xdbl,         p_dtrh,        p_dtrl};
        GArg a1{p_xch + tokDI, p_xcl + tokDI, p_wx + wx1, nullptr, p_xdbl + tokXD, p_dtrh + dtr1, p_dtrl + dtr1};
        dim3 grid(1, NTOK / BM, 2);
        gemm_sp<<<grid, 512, NSTAGE*STAGE_B>>>(a0, a1, D_INNER, D_INNER, XDBL_C, NTOK, XDBL_C, D_INNER, 2);
    }

    // dt_proj both dirs (16384 x 1536, K=48) + softplus
    {
        GArg a0{p_dtrh,        p_dtrl,        p_wd,       dt_proj_bias,   p_dt,         nullptr, nullptr};
        GArg a1{p_dtrh + dtr1, p_dtrl + dtr1, p_wd + wd1, dt_proj_bias_b, p_dt + tokDI, nullptr, nullptr};
        dim3 grid(D_INNER / BN, NTOK / BM, 2);
        gemm_sp<<<grid, 512, NSTAGE*STAGE_B>>>(a0, a1, DT_RANK, DT_RANK, D_INNER, NTOK, D_INNER, DT_RANK, 1);
    }

    // selective scan
    {
        dim3 grid(D_INNER / 128, B_SZ, 2);
        scan_kernel<<<grid, 128>>>(A_log, Dvec, A_log_b, D_b);
    }

    // ysum = split(y_f + y_b)
    cvt_add_split<<<2048, 256>>>(p_y, p_y + tokDI, p_ysh, p_ysl, (int)(tokDI / 4));

    // out_proj (16384 x 768, K=1536)
    {
        GArg a{p_ysh, p_ysl, p_wo, nullptr, out, nullptr, nullptr};
        dim3 grid(DIM / BN, NTOK / BM, 1);
        gemm_sp<<<grid, 512, NSTAGE*STAGE_B>>>(a, a, D_INNER, D_INNER, DIM, NTOK, DIM, D_INNER, 0);
    }
}

// round 7
// speedup vs baseline: 2.5438x; 2.5438x over previous
#include <cuda_runtime.h>
#include <cuda_fp16.h>
#include <cstdint>

// ---------------- Problem constants ----------------
#define B_SZ     4
#define L_SZ     4096
#define DIM      768
#define D_STATE  16
#define D_CONV   4
#define D_INNER  1536
#define DT_RANK  48
#define E2       (2*D_INNER) // 3072
#define NTOK     (B_SZ*L_SZ) // 16384
#define XDBL_C   (DT_RANK + 2*D_STATE) // 80

// ---------------- Scratch ----------------
__device__ float g_xz  [(size_t)NTOK * E2];
__device__ float g_dt  [2 * (size_t)NTOK * D_INNER];
__device__ float g_xdbl[2 * (size_t)NTOK * XDBL_C];
__device__ float g_y   [2 * (size_t)NTOK * D_INNER];

__device__ __align__(16) __half s_xh [(size_t)NTOK * DIM];
__device__ __align__(16) __half s_xl [(size_t)NTOK * DIM];
__device__ __align__(16) __half s_wi [(size_t)E2 * DIM];
__device__ __align__(16) __half s_wo [(size_t)DIM * D_INNER];
__device__ __align__(16) __half s_wx [2 * (size_t)XDBL_C * D_INNER];
__device__ __align__(16) __half s_wd [2 * (size_t)D_INNER * DT_RANK];
__device__ __align__(16) __half s_xch[2 * (size_t)NTOK * D_INNER];
__device__ __align__(16) __half s_xcl[2 * (size_t)NTOK * D_INNER];
__device__ __align__(16) __half s_dtrh[2 * (size_t)NTOK * DT_RANK];
__device__ __align__(16) __half s_dtrl[2 * (size_t)NTOK * DT_RANK];
__device__ __align__(16) __half s_ysh[(size_t)NTOK * D_INNER];
__device__ __align__(16) __half s_ysl[(size_t)NTOK * D_INNER];

// ---------------- helpers ----------------
__device__ __forceinline__ float softplusf(float x) {
    return (x > 20.f) ? x : log1pf(__expf(x));
}
__device__ __forceinline__ float siluf(float x) {
    return x / (1.f + __expf(-x));
}
__device__ __forceinline__ uint32_t smem_u32(const void* p) {
    uint32_t a;
    asm("{ .reg .u64 t; cvta.to.shared.u64 t, %1; cvt.u32.u64 %0, t; }" : "=r"(a) : "l"(p));
    return a;
}
__device__ __forceinline__ void ldsm4(uint32_t* r, uint32_t addr) {
    asm volatile("ldmatrix.sync.aligned.m8n8.x4.shared.b16 {%0,%1,%2,%3}, [%4];"
        : "=r"(r[0]), "=r"(r[1]), "=r"(r[2]), "=r"(r[3]) : "r"(addr));
}
__device__ __forceinline__ void mma_f16(float* c, const uint32_t* a, const uint32_t* b) {
    asm volatile("mma.sync.aligned.m16n8k16.row.col.f32.f16.f16.f32 "
        "{%0,%1,%2,%3}, {%4,%5,%6,%7}, {%8,%9}, {%0,%1,%2,%3};"
        : "+f"(c[0]), "+f"(c[1]), "+f"(c[2]), "+f"(c[3])
        : "r"(a[0]), "r"(a[1]), "r"(a[2]), "r"(a[3]), "r"(b[0]), "r"(b[1]));
}
__device__ __forceinline__ void cp16(uint32_t dst, const void* src, bool pred) {
    const int sz = pred ? 16 : 0;
    asm volatile("cp.async.cg.shared.global [%0], [%1], 16, %2;"
        :: "r"(dst), "l"(src), "r"(sz) : "memory");
}
__device__ __forceinline__ void split2h(float v, __half& h, __half& l) {
    h = __float2half_rn(v);
    l = __float2half_rn(v - __half2float(h));
}

// ---------------- conversion kernels ----------------
__global__ void cvt_split(const float* __restrict__ src,
                          __half* __restrict__ h, __half* __restrict__ l, int n4)
{
    for (int i = blockIdx.x * blockDim.x + threadIdx.x; i < n4; i += gridDim.x * blockDim.x) {
        float4 v = ((const float4*)src)[i];
        __half h0,h1,h2,h3,l0,l1,l2,l3;
        split2h(v.x,h0,l0); split2h(v.y,h1,l1); split2h(v.z,h2,l2); split2h(v.w,h3,l3);
        __half2 hh01{h0,h1}, hh23{h2,h3}, ll01{l0,l1}, ll23{l2,l3};
        ((uint2*)h)[i] = make_uint2(*(uint32_t*)&hh01, *(uint32_t*)&hh23);
        ((uint2*)l)[i] = make_uint2(*(uint32_t*)&ll01, *(uint32_t*)&ll23);
    }
}

__global__ void cvt_h(const float* __restrict__ src, __half* __restrict__ h, int n4)
{
    for (int i = blockIdx.x * blockDim.x + threadIdx.x; i < n4; i += gridDim.x * blockDim.x) {
        float4 v = ((const float4*)src)[i];
        __half2 a{__float2half_rn(v.x), __float2half_rn(v.y)};
        __half2 b{__float2half_rn(v.z), __float2half_rn(v.w)};
        ((uint2*)h)[i] = make_uint2(*(uint32_t*)&a, *(uint32_t*)&b);
    }
}

__global__ void cvt_h2(const float* __restrict__ s0, __half* __restrict__ d0,
                       const float* __restrict__ s1, __half* __restrict__ d1, int n4)
{
    const float* src = blockIdx.y ? s1 : s0;
    __half* h = blockIdx.y ? d1 : d0;
    for (int i = blockIdx.x * blockDim.x + threadIdx.x; i < n4; i += gridDim.x * blockDim.x) {
        float4 v = ((const float4*)src)[i];
        __half2 a{__float2half_rn(v.x), __float2half_rn(v.y)};
        __half2 b{__float2half_rn(v.z), __float2half_rn(v.w)};
        ((uint2*)h)[i] = make_uint2(*(uint32_t*)&a, *(uint32_t*)&b);
    }
}

__global__ void cvt_add_split(const float* __restrict__ a, const float* __restrict__ b,
                              __half* __restrict__ h, __half* __restrict__ l, int n4)
{
    for (int i = blockIdx.x * blockDim.x + threadIdx.x; i < n4; i += gridDim.x * blockDim.x) {
        float4 va = ((const float4*)a)[i];
        float4 vb = ((const float4*)b)[i];
        va.x += vb.x; va.y += vb.y; va.z += vb.z; va.w += vb.w;
        __half h0,h1,h2,h3,l0,l1,l2,l3;
        split2h(va.x,h0,l0); split2h(va.y,h1,l1); split2h(va.z,h2,l2); split2h(va.w,h3,l3);
        __half2 hh01{h0,h1}, hh23{h2,h3}, ll01{l0,l1}, ll23{l2,l3};
        ((uint2*)h)[i] = make_uint2(*(uint32_t*)&hh01, *(uint32_t*)&hh23);
        ((uint2*)l)[i] = make_uint2(*(uint32_t*)&ll01, *(uint32_t*)&ll23);
    }
}

// ---------------- 128x256 2-pass fp16-split HMMA GEMM, 4-stage cp.async ----------------
#define BM 128
#define BN 256
#define BKC 32
#define PAD 40
#define OFF_AH 0
#define OFF_AL 10240
#define OFF_B  20480
#define STAGE_B 40960
#define NSTAGE 4

struct GArg {
    const __half *Ah, *Al, *Bh;
    const float* bias;
    float* C;
    __half *Dh, *Dl;
};

__global__ __launch_bounds__(512, 1) void gemm_sp(
    GArg g0, GArg g1, int lda, int ldb, int ldc, int M, int N, int K, int epi)
{
    extern __shared__ char smem[];
    const uint32_t sbase = smem_u32(smem);
    const GArg g = (blockIdx.z == 0) ? g0 : g1;

    const int tid  = threadIdx.x;
    const int lane = tid & 31;
    const int wid  = tid >> 5;
    const int warpM = wid & 3;
    const int warpN = wid >> 2;

    int bmb, bnb;
    {
        const int nbn = gridDim.x;
        const int bid = blockIdx.y * nbn + blockIdx.x;
        const int per = 8 * nbn;
        const int grp = bid / per;
        const int r   = bid % per;
        bmb = grp * 8 + (r % 8);
        bnb = r / 8;
    }
    const int bm = bmb * BM;
    const int bn = bnb * BN;

    float acc[2][8][4];
    #pragma unroll
    for (int f = 0; f < 2; f++)
        #pragma unroll
        for (int gg = 0; gg < 8; gg++)
            #pragma unroll
            for (int i = 0; i < 4; i++) acc[f][gg][i] = 0.f;

    const int aRow = warpM * 32 + (lane & 15);
    const int aCol = (lane >> 4) * 8;
    const int bRow = warpN * 64 + (lane & 7) + ((lane >> 4) & 1) * 8;
    const int bCol = ((lane >> 3) & 1) * 8;

    const int nch = (K + BKC - 1) / BKC;

    auto issue = [&](int c) {
        if (c < nch) {
            const int k0 = c * BKC;
            const uint32_t st = sbase + (c % NSTAGE) * STAGE_B;
            const int r   = tid >> 2;
            const int c16 = tid & 3;
            const int kk  = k0 + c16 * 8;
            const bool vK = kk < K;
            const size_t ao = vK ? ((size_t)(bm + r) * lda + kk) : 0;
            const uint32_t soA = (uint32_t)(r * (PAD * 2) + c16 * 16);
            cp16(st + OFF_AH + soA, g.Ah + ao, vK);
            cp16(st + OFF_AL + soA, g.Al + ao, vK);
            #pragma unroll
            for (int it = 0; it < 2; it++) {
                const int row = r + 128 * it;
                const bool vB = vK && ((bn + row) < N);
                const size_t bo = vB ? ((size_t)(bn + row) * ldb + kk) : 0;
                cp16(st + OFF_B + (uint32_t)(row * (PAD * 2) + c16 * 16), g.Bh + bo, vB);
            }
        }
        asm volatile("cp.async.commit_group;" ::: "memory");
    };

    issue(0); issue(1); issue(2);

    for (int c = 0; c < nch; c++) {
        asm volatile("cp.async.wait_group 2;" ::: "memory");
        __syncthreads();

        const uint32_t st = sbase + (c % NSTAGE) * STAGE_B;
        #pragma unroll
        for (int ks = 0; ks < 2; ks++) {
            const int kc = ks * 16;
            uint32_t bfr[8][2], afr[2][4];
            #pragma unroll
            for (int p = 0; p < 4; p++) {
                uint32_t r4[4];
                ldsm4(r4, st + OFF_B + (uint32_t)((bRow + p*16) * PAD + kc + bCol) * 2);
                bfr[2*p][0] = r4[0]; bfr[2*p][1] = r4[1];
                bfr[2*p+1][0] = r4[2]; bfr[2*p+1][1] = r4[3];
            }
            #pragma unroll
            for (int f = 0; f < 2; f++)
                ldsm4(afr[f], st + OFF_AH + (uint32_t)((aRow + f*16) * PAD + kc + aCol) * 2);
            #pragma unroll
            for (int f = 0; f < 2; f++)
                #pragma unroll
                for (int gg = 0; gg < 8; gg++) mma_f16(acc[f][gg], afr[f], bfr[gg]);
            #pragma unroll
            for (int f = 0; f < 2; f++)
                ldsm4(afr[f], st + OFF_AL + (uint32_t)((aRow + f*16) * PAD + kc + aCol) * 2);
            #pragma unroll
            for (int f = 0; f < 2; f++)
                #pragma unroll
                for (int gg = 0; gg < 8; gg++) mma_f16(acc[f][gg], afr[f], bfr[gg]);
        }
        __syncthreads();
        issue(c + 3);
    }

    #pragma unroll
    for (int f = 0; f < 2; f++) {
        const int r0 = bm + warpM * 32 + f * 16 + (lane >> 2);
        #pragma unroll
        for (int gg = 0; gg < 8; gg++) {
            const int col = bn + warpN * 64 + gg * 8 + 2 * (lane & 3);
            if (col < N) {
                float v0 = acc[f][gg][0], v1 = acc[f][gg][1];
                float v2 = acc[f][gg][2], v3 = acc[f][gg][3];
                if (g.bias) {
                    const float b0 = g.bias[col], b1 = g.bias[col + 1];
                    v0 += b0; v1 += b1; v2 += b0; v3 += b1;
                }
                if (epi == 1) {
                    v0 = softplusf(v0); v1 = softplusf(v1);
                    v2 = softplusf(v2); v3 = softplusf(v3);
                }
                *(float2*)(g.C + (size_t)r0 * ldc + col)       = make_float2(v0, v1);
                *(float2*)(g.C + (size_t)(r0 + 8) * ldc + col) = make_float2(v2, v3);
                if (epi == 2 && col < DT_RANK) {
                    __half h0,l0,h1,l1,h2,l2,h3,l3;
                    split2h(v0,h0,l0); split2h(v1,h1,l1);
                    split2h(v2,h2,l2); split2h(v3,h3,l3);
                    __half2 ha{h0,h1}, la{l0,l1}, hb{h2,h3}, lb{l2,l3};
                    *(__half2*)(g.Dh + (size_t)r0 * DT_RANK + col)       = ha;
                    *(__half2*)(g.Dl + (size_t)r0 * DT_RANK + col)       = la;
                    *(__half2*)(g.Dh + (size_t)(r0 + 8) * DT_RANK + col) = hb;
                    *(__half2*)(g.Dl + (size_t)(r0 + 8) * DT_RANK + col) = lb;
                }
            }
        }
    }
}

// ---------------- Causal depthwise conv (k=4) + SiLU -> split fp16 ----------------
__global__ void conv_silu_kernel(
    const float* __restrict__ wf, const float* __restrict__ bf,
    const float* __restrict__ wb, const float* __restrict__ bb)
{
    const int dir = blockIdx.y;
    const size_t idx = (size_t)blockIdx.x * blockDim.x + threadIdx.x;
    if (idx >= (size_t)NTOK * D_INNER) return;
    const int d = (int)(idx % D_INNER);
    const size_t bl = idx / D_INNER;
    const int l = (int)(bl % L_SZ);
    const int b = (int)(bl / L_SZ);

    const float* w = dir ? wb : wf;
    float acc = dir ? bb[d] : bf[d];
    #pragma unroll
    for (int j = 0; j < D_CONV; j++) {
        const int m = l - (D_CONV - 1) + j;
        if (m >= 0) {
            const int src = dir ? (L_SZ - 1 - m) : m;
            acc += w[d * D_CONV + j] * g_xz[((size_t)b * L_SZ + src) * E2 + d];
        }
    }
    const float v = siluf(acc);
    __half h, lo;
    split2h(v, h, lo);
    const size_t o = ((size_t)dir * NTOK + bl) * D_INNER + d;
    s_xch[o] = h;
    s_xcl[o] = lo;
}

// ---------------- Selective scan v2: smem-staged, 4-way state split ----------------
// Block: 256 threads = 64 channels x 4 state-groups. Grid: (D_INNER/64, B_SZ, 2).
#define ST  64   // steps per chunk
#define SCH 64   // channels per block

__global__ __launch_bounds__(256) void scan_kernel(
    const float* __restrict__ A_log_f, const float* __restrict__ D_f,
    const float* __restrict__ A_log_b, const float* __restrict__ D_b)
{
    const int dir = blockIdx.z;
    const int b   = blockIdx.y;
    const int d0  = blockIdx.x * SCH;
    const int tid = threadIdx.x;
    const int ch  = tid >> 2;       // 0..63
    const int sg  = tid & 3;        // state group (4 states)
    const int d   = d0 + ch;

    const size_t dirTok = (size_t)dir * NTOK;
    const __half* xch = s_xch + dirTok * D_INNER;
    const __half* xcl = s_xcl + dirTok * D_INNER;
    const float* dtp  = g_dt   + dirTok * D_INNER;
    const float* xdbl = g_xdbl + dirTok * XDBL_C;
    float*       yout = g_y    + dirTok * D_INNER;
    const float* Alog = dir ? A_log_b : A_log_f;
    const float* Dv   = dir ? D_b     : D_f;

    float A[4];
    #pragma unroll
    for (int j = 0; j < 4; j++) A[j] = -__expf(Alog[d * D_STATE + sg * 4 + j]);
    const float Dd = Dv[d];

    float h[4] = {0.f, 0.f, 0.f, 0.f};

    __shared__ float s_u [ST][SCH];
    __shared__ float s_dt[ST][SCH];
    __shared__ float s_z [ST][SCH];
    __shared__ __align__(16) float s_B[ST][D_STATE];
    __shared__ __align__(16) float s_C[ST][D_STATE];

    for (int l0 = 0; l0 < L_SZ; l0 += ST) {
        __syncthreads();
        // stage u, dt, z (coalesced, deep MLP)
        #pragma unroll
        for (int i = tid; i < ST * SCH; i += 256) {
            const int t = i >> 6;
            const int c = i & 63;
            const size_t gl = ((size_t)b * L_SZ + l0 + t) * D_INNER + d0 + c;
            s_u[t][c]  = __half2float(xch[gl]) + __half2float(xcl[gl]);
            s_dt[t][c] = dtp[gl];
            const int lsrc = dir ? (L_SZ - 1 - (l0 + t)) : (l0 + t);
            s_z[t][c]  = g_xz[((size_t)b * L_SZ + lsrc) * E2 + D_INNER + d0 + c];
        }
        // stage B, C
        #pragma unroll
        for (int i = tid; i < ST * 32; i += 256) {
            const int t = i >> 5;
            const int c = i & 31;
            const float v = xdbl[((size_t)b * L_SZ + l0 + t) * XDBL_C + DT_RANK + c];
            if (c < D_STATE) s_B[t][c] = v;
            else             s_C[t][c - D_STATE] = v;
        }
        __syncthreads();

        for (int t = 0; t < ST; t++) {
            const float u   = s_u[t][ch];
            const float dtv = s_dt[t][ch];
            const float dtu = dtv * u;
            const float4 Bv = *(const float4*)&s_B[t][sg * 4];
            const float4 Cv = *(const float4*)&s_C[t][sg * 4];
            float y = 0.f;
            {
                const float dA0 = __expf(dtv * A[0]);
                const float dA1 = __expf(dtv * A[1]);
                const float dA2 = __expf(dtv * A[2]);
                const float dA3 = __expf(dtv * A[3]);
                h[0] = h[0] * dA0 + dtu * Bv.x;
                h[1] = h[1] * dA1 + dtu * Bv.y;
                h[2] = h[2] * dA2 + dtu * Bv.z;
                h[3] = h[3] * dA3 + dtu * Bv.w;
                y = h[0] * Cv.x + h[1] * Cv.y + h[2] * Cv.z + h[3] * Cv.w;
            }
            y += __shfl_xor_sync(0xFFFFFFFF, y, 1);
            y += __shfl_xor_sync(0xFFFFFFFF, y, 2);
            if (sg == 0) {
                y += u * Dd;
                const int l = l0 + t;
                const int lsrc = dir ? (L_SZ - 1 - l) : l;
                const float zv = s_z[t][ch];
                yout[((size_t)b * L_SZ + lsrc) * D_INNER + d] = y * siluf(zv);
            }
        }
    }
}

// ---------------- Launch ----------------
extern "C" void kernel_launch(void* const* d_in, const int* in_sizes, int n_in,
                              void* d_out, int out_size)
{
    const float* x            = (const float*)d_in[0];
    const float* in_proj_w    = (const float*)d_in[1];
    const float* out_proj_w   = (const float*)d_in[2];
    const float* conv1d_w     = (const float*)d_in[3];
    const float* conv1d_bias  = (const float*)d_in[4];
    const float* x_proj_w     = (const float*)d_in[5];
    const float* dt_proj_w    = (const float*)d_in[6];
    const float* dt_proj_bias = (const float*)d_in[7];
    const float* A_log        = (const float*)d_in[8];
    const float* Dvec         = (const float*)d_in[9];
    const float* conv1d_w_b   = (const float*)d_in[10];
    const float* conv1d_bias_b= (const float*)d_in[11];
    const float* x_proj_w_b   = (const float*)d_in[12];
    const float* dt_proj_w_b  = (const float*)d_in[13];
    const float* dt_proj_bias_b=(const float*)d_in[14];
    const float* A_log_b      = (const float*)d_in[15];
    const float* D_b          = (const float*)d_in[16];
    float* out = (float*)d_out;

    float *p_xz, *p_dt, *p_xdbl, *p_y;
    __half *p_xh,*p_xl,*p_wi,*p_wo,*p_wx,*p_wd,*p_xch,*p_xcl,*p_dtrh,*p_dtrl,*p_ysh,*p_ysl;
    cudaGetSymbolAddress((void**)&p_xz,   g_xz);
    cudaGetSymbolAddress((void**)&p_dt,   g_dt);
    cudaGetSymbolAddress((void**)&p_xdbl, g_xdbl);
    cudaGetSymbolAddress((void**)&p_y,    g_y);
    cudaGetSymbolAddress((void**)&p_xh,  s_xh);   cudaGetSymbolAddress((void**)&p_xl,  s_xl);
    cudaGetSymbolAddress((void**)&p_wi,  s_wi);
    cudaGetSymbolAddress((void**)&p_wo,  s_wo);
    cudaGetSymbolAddress((void**)&p_wx,  s_wx);
    cudaGetSymbolAddress((void**)&p_wd,  s_wd);
    cudaGetSymbolAddress((void**)&p_xch, s_xch);  cudaGetSymbolAddress((void**)&p_xcl, s_xcl);
    cudaGetSymbolAddress((void**)&p_dtrh,s_dtrh); cudaGetSymbolAddress((void**)&p_dtrl,s_dtrl);
    cudaGetSymbolAddress((void**)&p_ysh, s_ysh);  cudaGetSymbolAddress((void**)&p_ysl, s_ysl);

    cudaFuncSetAttribute(gemm_sp, cudaFuncAttributeMaxDynamicSharedMemorySize, NSTAGE * STAGE_B);

    const size_t tokDI = (size_t)NTOK * D_INNER;
    const size_t tokXD = (size_t)NTOK * XDBL_C;
    const size_t wx1   = (size_t)XDBL_C * D_INNER;
    const size_t wd1   = (size_t)D_INNER * DT_RANK;
    const size_t dtr1  = (size_t)NTOK * DT_RANK;

    // launches 1-5: conversions
    cvt_h2<<<dim3(128, 2), 256>>>(x_proj_w, p_wx, x_proj_w_b, p_wx + wx1, (int)(wx1 / 4));
    cvt_h2<<<dim3(128, 2), 256>>>(dt_proj_w, p_wd, dt_proj_w_b, p_wd + wd1, (int)(wd1 / 4));
    cvt_h<<< 512, 256>>>(out_proj_w, p_wo, DIM * D_INNER / 4);
    cvt_split<<<2048, 256>>>(x, p_xh, p_xl, NTOK * DIM / 4);
    cvt_h<<<1024, 256>>>(in_proj_w, p_wi, E2 * DIM / 4);

    // 6) in_proj (16384 x 3072, K=768) single launch  <-- profiled
    {
        GArg a{p_xh, p_xl, p_wi, nullptr, p_xz, nullptr, nullptr};
        dim3 grid(E2 / BN, NTOK / BM, 1);
        gemm_sp<<<grid, 512, NSTAGE*STAGE_B>>>(a, a, DIM, DIM, E2, NTOK, E2, DIM, 0);
    }

    // 7) conv + silu -> split fp16
    {
        dim3 grid((unsigned)(((size_t)NTOK * D_INNER + 255) / 256), 2);
        conv_silu_kernel<<<grid, 256>>>(conv1d_w, conv1d_bias, conv1d_w_b, conv1d_bias_b);
    }

    // 8) x_proj both dirs (16384 x 80, K=1536), epilogue splits dt_r
    {
        GArg a0{p_xch,         p_xcl,         p_wx,       nullptr, p_xdbl,         p_dtrh,        p_dtrl};
        GArg a1{p_xch + tokDI, p_xcl + tokDI, p_wx + wx1, nullptr, p_xdbl + tokXD, p_dtrh + dtr1, p_dtrl + dtr1};
        dim3 grid(1, NTOK / BM, 2);
        gemm_sp<<<grid, 512, NSTAGE*STAGE_B>>>(a0, a1, D_INNER, D_INNER, XDBL_C, NTOK, XDBL_C, D_INNER, 2);
    }

    // 9) dt_proj both dirs (16384 x 1536, K=48) + softplus
    {
        GArg a0{p_dtrh,        p_dtrl,        p_wd,       dt_proj_bias,   p_dt,         nullptr, nullptr};
        GArg a1{p_dtrh + dtr1, p_dtrl + dtr1, p_wd + wd1, dt_proj_bias_b, p_dt + tokDI, nullptr, nullptr};
        dim3 grid(D_INNER / BN, NTOK / BM, 2);
        gemm_sp<<<grid, 512, NSTAGE*STAGE_B>>>(a0, a1, DT_RANK, DT_RANK, D_INNER, NTOK, D_INNER, DT_RANK, 1);
    }

    // 10) selective scan v2
    {
        dim3 grid(D_INNER / SCH, B_SZ, 2);
        scan_kernel<<<grid, 256>>>(A_log, Dvec, A_log_b, D_b);
    }

    // 11) ysum = split(y_f + y_b)
    cvt_add_split<<<2048, 256>>>(p_y, p_y + tokDI, p_ysh, p_ysl, (int)(tokDI / 4));

    // 12) out_proj (16384 x 768, K=1536)
    {
        GArg a{p_ysh, p_ysl, p_wo, nullptr, out, nullptr, nullptr};
        dim3 grid(DIM / BN, NTOK / BM, 1);
        gemm_sp<<<grid, 512, NSTAGE*STAGE_B>>>(a, a, D_INNER, D_INNER, DIM, NTOK, DIM, D_INNER, 0);
    }
}

// round 8
// speedup vs baseline: 2.7276x; 1.0723x over previous
#include <cuda_runtime.h>
#include <cuda_fp16.h>
#include <cstdint>

// ---------------- Problem constants ----------------
#define B_SZ     4
#define L_SZ     4096
#define DIM      768
#define D_STATE  16
#define D_CONV   4
#define D_INNER  1536
#define DT_RANK  48
#define E2       (2*D_INNER) // 3072
#define NTOK     (B_SZ*L_SZ) // 16384
#define XDBL_C   (DT_RANK + 2*D_STATE) // 80

// ---------------- Scratch ----------------
__device__ float g_xz  [(size_t)NTOK * E2];
__device__ float g_dt  [2 * (size_t)NTOK * D_INNER];
__device__ float g_xdbl[2 * (size_t)NTOK * XDBL_C];
__device__ float g_y   [2 * (size_t)NTOK * D_INNER];

__device__ __align__(16) __half s_xh [(size_t)NTOK * DIM];
__device__ __align__(16) __half s_xl [(size_t)NTOK * DIM];
__device__ __align__(16) __half s_wi [(size_t)E2 * DIM];
__device__ __align__(16) __half s_wo [(size_t)DIM * D_INNER];
__device__ __align__(16) __half s_wx [2 * (size_t)XDBL_C * D_INNER];
__device__ __align__(16) __half s_wd [2 * (size_t)D_INNER * DT_RANK];
__device__ __align__(16) __half s_xch[2 * (size_t)NTOK * D_INNER];
__device__ __align__(16) __half s_xcl[2 * (size_t)NTOK * D_INNER];
__device__ __align__(16) __half s_dtrh[2 * (size_t)NTOK * DT_RANK];
__device__ __align__(16) __half s_dtrl[2 * (size_t)NTOK * DT_RANK];
__device__ __align__(16) __half s_ysh[(size_t)NTOK * D_INNER];
__device__ __align__(16) __half s_ysl[(size_t)NTOK * D_INNER];

// ---------------- helpers ----------------
__device__ __forceinline__ float softplusf(float x) {
    return (x > 20.f) ? x : log1pf(__expf(x));
}
__device__ __forceinline__ float siluf(float x) {
    return x / (1.f + __expf(-x));
}
__device__ __forceinline__ uint32_t smem_u32(const void* p) {
    uint32_t a;
    asm("{ .reg .u64 t; cvta.to.shared.u64 t, %1; cvt.u32.u64 %0, t; }" : "=r"(a) : "l"(p));
    return a;
}
__device__ __forceinline__ void ldsm4(uint32_t* r, uint32_t addr) {
    asm volatile("ldmatrix.sync.aligned.m8n8.x4.shared.b16 {%0,%1,%2,%3}, [%4];"
        : "=r"(r[0]), "=r"(r[1]), "=r"(r[2]), "=r"(r[3]) : "r"(addr));
}
__device__ __forceinline__ void mma_f16(float* c, const uint32_t* a, const uint32_t* b) {
    asm volatile("mma.sync.aligned.m16n8k16.row.col.f32.f16.f16.f32 "
        "{%0,%1,%2,%3}, {%4,%5,%6,%7}, {%8,%9}, {%0,%1,%2,%3};"
        : "+f"(c[0]), "+f"(c[1]), "+f"(c[2]), "+f"(c[3])
        : "r"(a[0]), "r"(a[1]), "r"(a[2]), "r"(a[3]), "r"(b[0]), "r"(b[1]));
}
__device__ __forceinline__ void cp16(uint32_t dst, const void* src, bool pred) {
    const int sz = pred ? 16 : 0;
    asm volatile("cp.async.cg.shared.global [%0], [%1], 16, %2;"
        :: "r"(dst), "l"(src), "r"(sz) : "memory");
}
__device__ __forceinline__ void split2h(float v, __half& h, __half& l) {
    h = __float2half_rn(v);
    l = __float2half_rn(v - __half2float(h));
}

// ---------------- conversion kernels ----------------
__global__ void cvt_split(const float* __restrict__ src,
                          __half* __restrict__ h, __half* __restrict__ l, int n4)
{
    for (int i = blockIdx.x * blockDim.x + threadIdx.x; i < n4; i += gridDim.x * blockDim.x) {
        float4 v = ((const float4*)src)[i];
        __half h0,h1,h2,h3,l0,l1,l2,l3;
        split2h(v.x,h0,l0); split2h(v.y,h1,l1); split2h(v.z,h2,l2); split2h(v.w,h3,l3);
        __half2 hh01{h0,h1}, hh23{h2,h3}, ll01{l0,l1}, ll23{l2,l3};
        ((uint2*)h)[i] = make_uint2(*(uint32_t*)&hh01, *(uint32_t*)&hh23);
        ((uint2*)l)[i] = make_uint2(*(uint32_t*)&ll01, *(uint32_t*)&ll23);
    }
}

__global__ void cvt_h(const float* __restrict__ src, __half* __restrict__ h, int n4)
{
    for (int i = blockIdx.x * blockDim.x + threadIdx.x; i < n4; i += gridDim.x * blockDim.x) {
        float4 v = ((const float4*)src)[i];
        __half2 a{__float2half_rn(v.x), __float2half_rn(v.y)};
        __half2 b{__float2half_rn(v.z), __float2half_rn(v.w)};
        ((uint2*)h)[i] = make_uint2(*(uint32_t*)&a, *(uint32_t*)&b);
    }
}

__global__ void cvt_h2(const float* __restrict__ s0, __half* __restrict__ d0,
                       const float* __restrict__ s1, __half* __restrict__ d1, int n4)
{
    const float* src = blockIdx.y ? s1 : s0;
    __half* h = blockIdx.y ? d1 : d0;
    for (int i = blockIdx.x * blockDim.x + threadIdx.x; i < n4; i += gridDim.x * blockDim.x) {
        float4 v = ((const float4*)src)[i];
        __half2 a{__float2half_rn(v.x), __float2half_rn(v.y)};
        __half2 b{__float2half_rn(v.z), __float2half_rn(v.w)};
        ((uint2*)h)[i] = make_uint2(*(uint32_t*)&a, *(uint32_t*)&b);
    }
}

__global__ void cvt_add_split(const float* __restrict__ a, const float* __restrict__ b,
                              __half* __restrict__ h, __half* __restrict__ l, int n4)
{
    for (int i = blockIdx.x * blockDim.x + threadIdx.x; i < n4; i += gridDim.x * blockDim.x) {
        float4 va = ((const float4*)a)[i];
        float4 vb = ((const float4*)b)[i];
        va.x += vb.x; va.y += vb.y; va.z += vb.z; va.w += vb.w;
        __half h0,h1,h2,h3,l0,l1,l2,l3;
        split2h(va.x,h0,l0); split2h(va.y,h1,l1); split2h(va.z,h2,l2); split2h(va.w,h3,l3);
        __half2 hh01{h0,h1}, hh23{h2,h3}, ll01{l0,l1}, ll23{l2,l3};
        ((uint2*)h)[i] = make_uint2(*(uint32_t*)&hh01, *(uint32_t*)&hh23);
        ((uint2*)l)[i] = make_uint2(*(uint32_t*)&ll01, *(uint32_t*)&ll23);
    }
}

// ---------------- 128x256 2-pass fp16-split HMMA GEMM, 5-stage cp.async ----------------
#define BM 128
#define BN 256
#define BKC 32
#define PAD 40
#define OFF_AH 0
#define OFF_AL 10240
#define OFF_B  20480
#define STAGE_B 40960
#define NSTAGE 5

struct GArg {
    const __half *Ah, *Al, *Bh;
    const float* bias;
    float* C;
    __half *Dh, *Dl;
};

__global__ __launch_bounds__(512, 1) void gemm_sp(
    GArg g0, GArg g1, int lda, int ldb, int ldc, int M, int N, int K, int epi)
{
    extern __shared__ char smem[];
    const uint32_t sbase = smem_u32(smem);
    const GArg g = (blockIdx.z == 0) ? g0 : g1;

    const int tid  = threadIdx.x;
    const int lane = tid & 31;
    const int wid  = tid >> 5;
    const int warpM = wid & 3;
    const int warpN = wid >> 2;

    int bmb, bnb;
    {
        const int nbn = gridDim.x;
        const int bid = blockIdx.y * nbn + blockIdx.x;
        const int per = 8 * nbn;
        const int grp = bid / per;
        const int r   = bid % per;
        bmb = grp * 8 + (r % 8);
        bnb = r / 8;
    }
    const int bm = bmb * BM;
    const int bn = bnb * BN;

    float acc[2][8][4];
    #pragma unroll
    for (int f = 0; f < 2; f++)
        #pragma unroll
        for (int gg = 0; gg < 8; gg++)
            #pragma unroll
            for (int i = 0; i < 4; i++) acc[f][gg][i] = 0.f;

    const int aRow = warpM * 32 + (lane & 15);
    const int aCol = (lane >> 4) * 8;
    const int bRow = warpN * 64 + (lane & 7) + ((lane >> 4) & 1) * 8;
    const int bCol = ((lane >> 3) & 1) * 8;

    const int nch = (K + BKC - 1) / BKC;

    auto issue = [&](int c) {
        if (c < nch) {
            const int k0 = c * BKC;
            const uint32_t st = sbase + (c % NSTAGE) * STAGE_B;
            const int r   = tid >> 2;
            const int c16 = tid & 3;
            const int kk  = k0 + c16 * 8;
            const bool vK = kk < K;
            const size_t ao = vK ? ((size_t)(bm + r) * lda + kk) : 0;
            const uint32_t soA = (uint32_t)(r * (PAD * 2) + c16 * 16);
            cp16(st + OFF_AH + soA, g.Ah + ao, vK);
            cp16(st + OFF_AL + soA, g.Al + ao, vK);
            #pragma unroll
            for (int it = 0; it < 2; it++) {
                const int row = r + 128 * it;
                const bool vB = vK && ((bn + row) < N);
                const size_t bo = vB ? ((size_t)(bn + row) * ldb + kk) : 0;
                cp16(st + OFF_B + (uint32_t)(row * (PAD * 2) + c16 * 16), g.Bh + bo, vB);
            }
        }
        asm volatile("cp.async.commit_group;" ::: "memory");
    };

    issue(0); issue(1); issue(2); issue(3);

    for (int c = 0; c < nch; c++) {
        asm volatile("cp.async.wait_group 3;" ::: "memory");
        __syncthreads();
        // safe: all warps finished reading stage (c-1) before this sync,
        // and issue(c+4) writes exactly stage (c-1)%NSTAGE.
        issue(c + 4);

        const uint32_t st = sbase + (c % NSTAGE) * STAGE_B;
        #pragma unroll
        for (int ks = 0; ks < 2; ks++) {
            const int kc = ks * 16;
            uint32_t bfr[8][2], afr[2][4];
            #pragma unroll
            for (int p = 0; p < 4; p++) {
                uint32_t r4[4];
                ldsm4(r4, st + OFF_B + (uint32_t)((bRow + p*16) * PAD + kc + bCol) * 2);
                bfr[2*p][0] = r4[0]; bfr[2*p][1] = r4[1];
                bfr[2*p+1][0] = r4[2]; bfr[2*p+1][1] = r4[3];
            }
            #pragma unroll
            for (int f = 0; f < 2; f++)
                ldsm4(afr[f], st + OFF_AH + (uint32_t)((aRow + f*16) * PAD + kc + aCol) * 2);
            #pragma unroll
            for (int f = 0; f < 2; f++)
                #pragma unroll
                for (int gg = 0; gg < 8; gg++) mma_f16(acc[f][gg], afr[f], bfr[gg]);
            #pragma unroll
            for (int f = 0; f < 2; f++)
                ldsm4(afr[f], st + OFF_AL + (uint32_t)((aRow + f*16) * PAD + kc + aCol) * 2);
            #pragma unroll
            for (int f = 0; f < 2; f++)
                #pragma unroll
                for (int gg = 0; gg < 8; gg++) mma_f16(acc[f][gg], afr[f], bfr[gg]);
        }
    }

    #pragma unroll
    for (int f = 0; f < 2; f++) {
        const int r0 = bm + warpM * 32 + f * 16 + (lane >> 2);
        #pragma unroll
        for (int gg = 0; gg < 8; gg++) {
            const int col = bn + warpN * 64 + gg * 8 + 2 * (lane & 3);
            if (col < N) {
                float v0 = acc[f][gg][0], v1 = acc[f][gg][1];
                float v2 = acc[f][gg][2], v3 = acc[f][gg][3];
                if (g.bias) {
                    const float b0 = g.bias[col], b1 = g.bias[col + 1];
                    v0 += b0; v1 += b1; v2 += b0; v3 += b1;
                }
                if (epi == 1) {
                    v0 = softplusf(v0); v1 = softplusf(v1);
                    v2 = softplusf(v2); v3 = softplusf(v3);
                }
                *(float2*)(g.C + (size_t)r0 * ldc + col)       = make_float2(v0, v1);
                *(float2*)(g.C + (size_t)(r0 + 8) * ldc + col) = make_float2(v2, v3);
                if (epi == 2 && col < DT_RANK) {
                    __half h0,l0,h1,l1,h2,l2,h3,l3;
                    split2h(v0,h0,l0); split2h(v1,h1,l1);
                    split2h(v2,h2,l2); split2h(v3,h3,l3);
                    __half2 ha{h0,h1}, la{l0,l1}, hb{h2,h3}, lb{l2,l3};
                    *(__half2*)(g.Dh + (size_t)r0 * DT_RANK + col)       = ha;
                    *(__half2*)(g.Dl + (size_t)r0 * DT_RANK + col)       = la;
                    *(__half2*)(g.Dh + (size_t)(r0 + 8) * DT_RANK + col) = hb;
                    *(__half2*)(g.Dl + (size_t)(r0 + 8) * DT_RANK + col) = lb;
                }
            }
        }
    }
}

// ---------------- Causal depthwise conv (k=4) + SiLU, smem-staged ----------------
#define CTOK 32
#define CCH  128
__global__ __launch_bounds__(256) void conv_silu_kernel(
    const float* __restrict__ wf, const float* __restrict__ bf,
    const float* __restrict__ wb, const float* __restrict__ bb)
{
    const int dir = blockIdx.z >> 2;
    const int b   = blockIdx.z & 3;
    const int l0  = blockIdx.y * CTOK;
    const int d0  = blockIdx.x * CCH;
    const int tid = threadIdx.x;

    __shared__ float sx[CTOK + 3][CCH];

    #pragma unroll
    for (int i = tid; i < (CTOK + 3) * CCH; i += 256) {
        const int r = i / CCH;
        const int c = i % CCH;
        const int m = l0 - 3 + r;
        float v = 0.f;
        if (m >= 0) {
            const int src = dir ? (L_SZ - 1 - m) : m;
            v = g_xz[((size_t)b * L_SZ + src) * E2 + d0 + c];
        }
        sx[r][c] = v;
    }
    __syncthreads();

    const int c  = tid & (CCH - 1);
    const int t0 = tid >> 7;     // 0..1
    const int d  = d0 + c;
    const float* w = dir ? wb : wf;
    const float w0 = w[d * 4 + 0], w1 = w[d * 4 + 1];
    const float w2 = w[d * 4 + 2], w3 = w[d * 4 + 3];
    const float bias = dir ? bb[d] : bf[d];

    #pragma unroll
    for (int t = t0; t < CTOK; t += 2) {
        const float acc = bias + w0 * sx[t][c] + w1 * sx[t + 1][c]
                               + w2 * sx[t + 2][c] + w3 * sx[t + 3][c];
        const float v = siluf(acc);
        __half h, lo;
        split2h(v, h, lo);
        const size_t o = ((size_t)dir * NTOK + (size_t)b * L_SZ + l0 + t) * D_INNER + d;
        s_xch[o] = h;
        s_xcl[o] = lo;
    }
}

// ---------------- Selective scan: smem-staged, 4-way state split ----------------
#define ST  64
#define SCH 64

__global__ __launch_bounds__(256) void scan_kernel(
    const float* __restrict__ A_log_f, const float* __restrict__ D_f,
    const float* __restrict__ A_log_b, const float* __restrict__ D_b)
{
    const int dir = blockIdx.z;
    const int b   = blockIdx.y;
    const int d0  = blockIdx.x * SCH;
    const int tid = threadIdx.x;
    const int ch  = tid >> 2;
    const int sg  = tid & 3;
    const int d   = d0 + ch;

    const size_t dirTok = (size_t)dir * NTOK;
    const __half* xch = s_xch + dirTok * D_INNER;
    const __half* xcl = s_xcl + dirTok * D_INNER;
    const float* dtp  = g_dt   + dirTok * D_INNER;
    const float* xdbl = g_xdbl + dirTok * XDBL_C;
    float*       yout = g_y    + dirTok * D_INNER;
    const float* Alog = dir ? A_log_b : A_log_f;
    const float* Dv   = dir ? D_b     : D_f;

    float A[4];
    #pragma unroll
    for (int j = 0; j < 4; j++) A[j] = -__expf(Alog[d * D_STATE + sg * 4 + j]);
    const float Dd = Dv[d];

    float h[4] = {0.f, 0.f, 0.f, 0.f};

    __shared__ float s_u [ST][SCH];
    __shared__ float s_dt[ST][SCH];
    __shared__ float s_z [ST][SCH];
    __shared__ __align__(16) float s_B[ST][D_STATE];
    __shared__ __align__(16) float s_C[ST][D_STATE];

    for (int l0 = 0; l0 < L_SZ; l0 += ST) {
        __syncthreads();
        #pragma unroll
        for (int i = tid; i < ST * SCH; i += 256) {
            const int t = i >> 6;
            const int c = i & 63;
            const size_t gl = ((size_t)b * L_SZ + l0 + t) * D_INNER + d0 + c;
            s_u[t][c]  = __half2float(xch[gl]) + __half2float(xcl[gl]);
            s_dt[t][c] = dtp[gl];
            const int lsrc = dir ? (L_SZ - 1 - (l0 + t)) : (l0 + t);
            s_z[t][c]  = g_xz[((size_t)b * L_SZ + lsrc) * E2 + D_INNER + d0 + c];
        }
        #pragma unroll
        for (int i = tid; i < ST * 32; i += 256) {
            const int t = i >> 5;
            const int c = i & 31;
            const float v = xdbl[((size_t)b * L_SZ + l0 + t) * XDBL_C + DT_RANK + c];
            if (c < D_STATE) s_B[t][c] = v;
            else             s_C[t][c - D_STATE] = v;
        }
        __syncthreads();

        for (int t = 0; t < ST; t++) {
            const float u   = s_u[t][ch];
            const float dtv = s_dt[t][ch];
            const float dtu = dtv * u;
            const float4 Bv = *(const float4*)&s_B[t][sg * 4];
            const float4 Cv = *(const float4*)&s_C[t][sg * 4];
            float y;
            {
                const float dA0 = __expf(dtv * A[0]);
                const float dA1 = __expf(dtv * A[1]);
                const float dA2 = __expf(dtv * A[2]);
                const float dA3 = __expf(dtv * A[3]);
                h[0] = h[0] * dA0 + dtu * Bv.x;
                h[1] = h[1] * dA1 + dtu * Bv.y;
                h[2] = h[2] * dA2 + dtu * Bv.z;
                h[3] = h[3] * dA3 + dtu * Bv.w;
                y = h[0] * Cv.x + h[1] * Cv.y + h[2] * Cv.z + h[3] * Cv.w;
            }
            y += __shfl_xor_sync(0xFFFFFFFF, y, 1);
            y += __shfl_xor_sync(0xFFFFFFFF, y, 2);
            if (sg == 0) {
                y += u * Dd;
                const int l = l0 + t;
                const int lsrc = dir ? (L_SZ - 1 - l) : l;
                const float zv = s_z[t][ch];
                yout[((size_t)b * L_SZ + lsrc) * D_INNER + d] = y * siluf(zv);
            }
        }
    }
}

// ---------------- Launch ----------------
extern "C" void kernel_launch(void* const* d_in, const int* in_sizes, int n_in,
                              void* d_out, int out_size)
{
    const float* x            = (const float*)d_in[0];
    const float* in_proj_w    = (const float*)d_in[1];
    const float* out_proj_w   = (const float*)d_in[2];
    const float* conv1d_w     = (const float*)d_in[3];
    const float* conv1d_bias  = (const float*)d_in[4];
    const float* x_proj_w     = (const float*)d_in[5];
    const float* dt_proj_w    = (const float*)d_in[6];
    const float* dt_proj_bias = (const float*)d_in[7];
    const float* A_log        = (const float*)d_in[8];
    const float* Dvec         = (const float*)d_in[9];
    const float* conv1d_w_b   = (const float*)d_in[10];
    const float* conv1d_bias_b= (const float*)d_in[11];
    const float* x_proj_w_b   = (const float*)d_in[12];
    const float* dt_proj_w_b  = (const float*)d_in[13];
    const float* dt_proj_bias_b=(const float*)d_in[14];
    const float* A_log_b      = (const float*)d_in[15];
    const float* D_b          = (const float*)d_in[16];
    float* out = (float*)d_out;

    float *p_xz, *p_dt, *p_xdbl, *p_y;
    __half *p_xh,*p_xl,*p_wi,*p_wo,*p_wx,*p_wd,*p_xch,*p_xcl,*p_dtrh,*p_dtrl,*p_ysh,*p_ysl;
    cudaGetSymbolAddress((void**)&p_xz,   g_xz);
    cudaGetSymbolAddress((void**)&p_dt,   g_dt);
    cudaGetSymbolAddress((void**)&p_xdbl, g_xdbl);
    cudaGetSymbolAddress((void**)&p_y,    g_y);
    cudaGetSymbolAddress((void**)&p_xh,  s_xh);   cudaGetSymbolAddress((void**)&p_xl,  s_xl);
    cudaGetSymbolAddress((void**)&p_wi,  s_wi);
    cudaGetSymbolAddress((void**)&p_wo,  s_wo);
    cudaGetSymbolAddress((void**)&p_wx,  s_wx);
    cudaGetSymbolAddress((void**)&p_wd,  s_wd);
    cudaGetSymbolAddress((void**)&p_xch, s_xch);  cudaGetSymbolAddress((void**)&p_xcl, s_xcl);
    cudaGetSymbolAddress((void**)&p_dtrh,s_dtrh); cudaGetSymbolAddress((void**)&p_dtrl,s_dtrl);
    cudaGetSymbolAddress((void**)&p_ysh, s_ysh);  cudaGetSymbolAddress((void**)&p_ysl, s_ysl);

    cudaFuncSetAttribute(gemm_sp, cudaFuncAttributeMaxDynamicSharedMemorySize, NSTAGE * STAGE_B);

    const size_t tokDI = (size_t)NTOK * D_INNER;
    const size_t tokXD = (size_t)NTOK * XDBL_C;
    const size_t wx1   = (size_t)XDBL_C * D_INNER;
    const size_t wd1   = (size_t)D_INNER * DT_RANK;
    const size_t dtr1  = (size_t)NTOK * DT_RANK;

    // conversions
    cvt_h2<<<dim3(128, 2), 256>>>(x_proj_w, p_wx, x_proj_w_b, p_wx + wx1, (int)(wx1 / 4));
    cvt_h2<<<dim3(128, 2), 256>>>(dt_proj_w, p_wd, dt_proj_w_b, p_wd + wd1, (int)(wd1 / 4));
    cvt_h<<< 512, 256>>>(out_proj_w, p_wo, DIM * D_INNER / 4);
    cvt_split<<<2048, 256>>>(x, p_xh, p_xl, NTOK * DIM / 4);
    cvt_h<<<1024, 256>>>(in_proj_w, p_wi, E2 * DIM / 4);

    // in_proj (16384 x 3072, K=768)
    {
        GArg a{p_xh, p_xl, p_wi, nullptr, p_xz, nullptr, nullptr};
        dim3 grid(E2 / BN, NTOK / BM, 1);
        gemm_sp<<<grid, 512, NSTAGE*STAGE_B>>>(a, a, DIM, DIM, E2, NTOK, E2, DIM, 0);
    }

    // conv + silu -> split fp16 (smem-staged)
    {
        dim3 grid(D_INNER / CCH, L_SZ / CTOK, 2 * B_SZ);
        conv_silu_kernel<<<grid, 256>>>(conv1d_w, conv1d_bias, conv1d_w_b, conv1d_bias_b);
    }

    // x_proj both dirs (16384 x 80, K=1536), epilogue splits dt_r
    {
        GArg a0{p_xch,         p_xcl,         p_wx,       nullptr, p_xdbl,         p_dtrh,        p_dtrl};
        GArg a1{p_xch + tokDI, p_xcl + tokDI, p_wx + wx1, nullptr, p_xdbl + tokXD, p_dtrh + dtr1, p_dtrl + dtr1};
        dim3 grid(1, NTOK / BM, 2);
        gemm_sp<<<grid, 512, NSTAGE*STAGE_B>>>(a0, a1, D_INNER, D_INNER, XDBL_C, NTOK, XDBL_C, D_INNER, 2);
    }

    // dt_proj both dirs (16384 x 1536, K=48) + softplus
    {
        GArg a0{p_dtrh,        p_dtrl,        p_wd,       dt_proj_bias,   p_dt,         nullptr, nullptr};
        GArg a1{p_dtrh + dtr1, p_dtrl + dtr1, p_wd + wd1, dt_proj_bias_b, p_dt + tokDI, nullptr, nullptr};
        dim3 grid(D_INNER / BN, NTOK / BM, 2);
        gemm_sp<<<grid, 512, NSTAGE*STAGE_B>>>(a0, a1, DT_RANK, DT_RANK, D_INNER, NTOK, D_INNER, DT_RANK, 1);
    }

    // selective scan
    {
        dim3 grid(D_INNER / SCH, B_SZ, 2);
        scan_kernel<<<grid, 256>>>(A_log, Dvec, A_log_b, D_b);
    }

    // ysum = split(y_f + y_b)
    cvt_add_split<<<2048, 256>>>(p_y, p_y + tokDI, p_ysh, p_ysl, (int)(tokDI / 4));

    // out_proj (16384 x 768, K=1536)
    {
        GArg a{p_ysh, p_ysl, p_wo, nullptr, out, nullptr, nullptr};
        dim3 grid(DIM / BN, NTOK / BM, 1);
        gemm_sp<<<grid, 512, NSTAGE*STAGE_B>>>(a, a, D_INNER, D_INNER, DIM, NTOK, DIM, D_INNER, 0);
    }
}

// round 9
// speedup vs baseline: 3.2877x; 1.2053x over previous
#include <cuda_runtime.h>
#include <cuda_fp16.h>
#include <cstdint>

// ---------------- Problem constants ----------------
#define B_SZ     4
#define L_SZ     4096
#define DIM      768
#define D_STATE  16
#define D_CONV   4
#define D_INNER  1536
#define DT_RANK  48
#define E2       (2*D_INNER) // 3072
#define NTOK     (B_SZ*L_SZ) // 16384
#define XDBL_C   (DT_RANK + 2*D_STATE) // 80

// ---------------- Scratch ----------------
__device__ float g_xz  [(size_t)NTOK * E2];
__device__ float g_dt  [2 * (size_t)NTOK * D_INNER];
__device__ float g_xdbl[2 * (size_t)NTOK * XDBL_C];
__device__ float g_y   [2 * (size_t)NTOK * D_INNER];

__device__ __align__(16) __half s_xh [(size_t)NTOK * DIM];
__device__ __align__(16) __half s_wi [(size_t)E2 * DIM];
__device__ __align__(16) __half s_wo [(size_t)DIM * D_INNER];
__device__ __align__(16) __half s_wx [2 * (size_t)XDBL_C * D_INNER];
__device__ __align__(16) __half s_wd [2 * (size_t)D_INNER * DT_RANK];
__device__ __align__(16) __half s_xch[2 * (size_t)NTOK * D_INNER];
__device__ __align__(16) __half s_dtrh[2 * (size_t)NTOK * DT_RANK];
__device__ __align__(16) __half s_ysh[(size_t)NTOK * D_INNER];

// ---------------- helpers ----------------
__device__ __forceinline__ float softplusf(float x) {
    return (x > 20.f) ? x : log1pf(__expf(x));
}
__device__ __forceinline__ float siluf(float x) {
    return x / (1.f + __expf(-x));
}
__device__ __forceinline__ uint32_t smem_u32(const void* p) {
    uint32_t a;
    asm("{ .reg .u64 t; cvta.to.shared.u64 t, %1; cvt.u32.u64 %0, t; }" : "=r"(a) : "l"(p));
    return a;
}
__device__ __forceinline__ void ldsm4(uint32_t* r, uint32_t addr) {
    asm volatile("ldmatrix.sync.aligned.m8n8.x4.shared.b16 {%0,%1,%2,%3}, [%4];"
        : "=r"(r[0]), "=r"(r[1]), "=r"(r[2]), "=r"(r[3]) : "r"(addr));
}
__device__ __forceinline__ void mma_f16(float* c, const uint32_t* a, const uint32_t* b) {
    asm volatile("mma.sync.aligned.m16n8k16.row.col.f32.f16.f16.f32 "
        "{%0,%1,%2,%3}, {%4,%5,%6,%7}, {%8,%9}, {%0,%1,%2,%3};"
        : "+f"(c[0]), "+f"(c[1]), "+f"(c[2]), "+f"(c[3])
        : "r"(a[0]), "r"(a[1]), "r"(a[2]), "r"(a[3]), "r"(b[0]), "r"(b[1]));
}
__device__ __forceinline__ void cp16(uint32_t dst, const void* src, bool pred) {
    const int sz = pred ? 16 : 0;
    asm volatile("cp.async.cg.shared.global [%0], [%1], 16, %2;"
        :: "r"(dst), "l"(src), "r"(sz) : "memory");
}

// ---------------- batched fp32 -> fp16 conversion (one launch) ----------------
#define NSEG 7
struct CvtSegs {
    const float* src[NSEG];
    __half* dst[NSEG];
    int n4[NSEG];
};

__global__ void cvt_all(CvtSegs a, int total4)
{
    const int stride = gridDim.x * blockDim.x;
    for (int i = blockIdx.x * blockDim.x + threadIdx.x; i < total4; i += stride) {
        int off = i, s = 0;
        while (s < NSEG - 1 && off >= a.n4[s]) { off -= a.n4[s]; s++; }
        float4 v = ((const float4*)a.src[s])[off];
        __half2 p{__float2half_rn(v.x), __float2half_rn(v.y)};
        __half2 q{__float2half_rn(v.z), __float2half_rn(v.w)};
        ((uint2*)a.dst[s])[off] = make_uint2(*(uint32_t*)&p, *(uint32_t*)&q);
    }
}

__global__ void cvt_add(const float* __restrict__ a, const float* __restrict__ b,
                        __half* __restrict__ h, int n4)
{
    const int stride = gridDim.x * blockDim.x;
    for (int i = blockIdx.x * blockDim.x + threadIdx.x; i < n4; i += stride) {
        float4 va = ((const float4*)a)[i];
        float4 vb = ((const float4*)b)[i];
        __half2 p{__float2half_rn(va.x + vb.x), __float2half_rn(va.y + vb.y)};
        __half2 q{__float2half_rn(va.z + vb.z), __float2half_rn(va.w + vb.w)};
        ((uint2*)h)[i] = make_uint2(*(uint32_t*)&p, *(uint32_t*)&q);
    }
}

// ---------------- single-pass fp16 HMMA GEMM, 5-stage cp.async, templated BN ----------------
#define BM 128
#define BKC 32
#define PAD 40
#define NSTAGE 5

struct GArg {
    const __half *Ah, *Bh;
    const float* bias;
    float* C;
    __half *Dh;
};

template<int BNT>
__global__ __launch_bounds__(512, 1) void gemm_sp(
    GArg g0, GArg g1, int lda, int ldb, int ldc, int M, int N, int K, int epi)
{
    constexpr int NF    = BNT / 32;           // n-frags per warp
    constexpr int OFF_B = 10240;              // A: 128 rows * 80B
    constexpr int STAGE = 10240 + BNT * 80;
    extern __shared__ char smem[];
    const uint32_t sbase = smem_u32(smem);
    const GArg g = (blockIdx.z == 0) ? g0 : g1;

    const int tid  = threadIdx.x;
    const int lane = tid & 31;
    const int wid  = tid >> 5;
    const int warpM = wid & 3;
    const int warpN = wid >> 2;

    int bmb, bnb;
    {
        const int nbn = gridDim.x;
        const int bid = blockIdx.y * nbn + blockIdx.x;
        const int per = 8 * nbn;
        const int grp = bid / per;
        const int r   = bid % per;
        bmb = grp * 8 + (r % 8);
        bnb = r / 8;
    }
    const int bm = bmb * BM;
    const int bn = bnb * BNT;

    float acc[2][NF][4];
    #pragma unroll
    for (int f = 0; f < 2; f++)
        #pragma unroll
        for (int gg = 0; gg < NF; gg++)
            #pragma unroll
            for (int i = 0; i < 4; i++) acc[f][gg][i] = 0.f;

    const int aRow = warpM * 32 + (lane & 15);
    const int aCol = (lane >> 4) * 8;
    const int bRow = warpN * (BNT / 4) + (lane & 7) + ((lane >> 4) & 1) * 8;
    const int bCol = ((lane >> 3) & 1) * 8;

    const int nch = (K + BKC - 1) / BKC;

    auto issue = [&](int c) {
        if (c < nch) {
            const int k0 = c * BKC;
            const uint32_t st = sbase + (c % NSTAGE) * STAGE;
            const int r   = tid >> 2;     // 0..127
            const int c16 = tid & 3;
            const int kk  = k0 + c16 * 8;
            const bool vK = kk < K;
            const size_t ao = vK ? ((size_t)(bm + r) * lda + kk) : 0;
            cp16(st + (uint32_t)(r * (PAD * 2) + c16 * 16), g.Ah + ao, vK);
            #pragma unroll
            for (int it = 0; it < BNT / 128; it++) {
                const int row = r + 128 * it;
                const bool vB = vK && ((bn + row) < N);
                const size_t bo = vB ? ((size_t)(bn + row) * ldb + kk) : 0;
                cp16(st + OFF_B + (uint32_t)(row * (PAD * 2) + c16 * 16), g.Bh + bo, vB);
            }
        }
        asm volatile("cp.async.commit_group;" ::: "memory");
    };

    issue(0); issue(1); issue(2); issue(3);

    for (int c = 0; c < nch; c++) {
        asm volatile("cp.async.wait_group 3;" ::: "memory");
        __syncthreads();
        issue(c + 4);

        const uint32_t st = sbase + (c % NSTAGE) * STAGE;
        #pragma unroll
        for (int ks = 0; ks < 2; ks++) {
            const int kc = ks * 16;
            uint32_t bfr[NF][2], afr[2][4];
            #pragma unroll
            for (int p = 0; p < NF / 2; p++) {
                uint32_t r4[4];
                ldsm4(r4, st + OFF_B + (uint32_t)((bRow + p*16) * PAD + kc + bCol) * 2);
                bfr[2*p][0] = r4[0]; bfr[2*p][1] = r4[1];
                bfr[2*p+1][0] = r4[2]; bfr[2*p+1][1] = r4[3];
            }
            #pragma unroll
            for (int f = 0; f < 2; f++)
                ldsm4(afr[f], st + (uint32_t)((aRow + f*16) * PAD + kc + aCol) * 2);
            #pragma unroll
            for (int f = 0; f < 2; f++)
                #pragma unroll
                for (int gg = 0; gg < NF; gg++) mma_f16(acc[f][gg], afr[f], bfr[gg]);
        }
    }

    #pragma unroll
    for (int f = 0; f < 2; f++) {
        const int r0 = bm + warpM * 32 + f * 16 + (lane >> 2);
        #pragma unroll
        for (int gg = 0; gg < NF; gg++) {
            const int col = bn + warpN * (BNT / 4) + gg * 8 + 2 * (lane & 3);
            if (col < N) {
                float v0 = acc[f][gg][0], v1 = acc[f][gg][1];
                float v2 = acc[f][gg][2], v3 = acc[f][gg][3];
                if (g.bias) {
                    const float b0 = g.bias[col], b1 = g.bias[col + 1];
                    v0 += b0; v1 += b1; v2 += b0; v3 += b1;
                }
                if (epi == 1) {
                    v0 = softplusf(v0); v1 = softplusf(v1);
                    v2 = softplusf(v2); v3 = softplusf(v3);
                }
                *(float2*)(g.C + (size_t)r0 * ldc + col)       = make_float2(v0, v1);
                *(float2*)(g.C + (size_t)(r0 + 8) * ldc + col) = make_float2(v2, v3);
                if (epi == 2 && col < DT_RANK) {
                    __half2 ha{__float2half_rn(v0), __float2half_rn(v1)};
                    __half2 hb{__float2half_rn(v2), __float2half_rn(v3)};
                    *(__half2*)(g.Dh + (size_t)r0 * DT_RANK + col)       = ha;
                    *(__half2*)(g.Dh + (size_t)(r0 + 8) * DT_RANK + col) = hb;
                }
            }
        }
    }
}

// ---------------- Causal depthwise conv (k=4) + SiLU, smem-staged ----------------
#define CTOK 32
#define CCH  128
__global__ __launch_bounds__(256) void conv_silu_kernel(
    const float* __restrict__ wf, const float* __restrict__ bf,
    const float* __restrict__ wb, const float* __restrict__ bb)
{
    const int dir = blockIdx.z >> 2;
    const int b   = blockIdx.z & 3;
    const int l0  = blockIdx.y * CTOK;
    const int d0  = blockIdx.x * CCH;
    const int tid = threadIdx.x;

    __shared__ float sx[CTOK + 3][CCH];

    #pragma unroll
    for (int i = tid; i < (CTOK + 3) * CCH; i += 256) {
        const int r = i / CCH;
        const int c = i % CCH;
        const int m = l0 - 3 + r;
        float v = 0.f;
        if (m >= 0) {
            const int src = dir ? (L_SZ - 1 - m) : m;
            v = g_xz[((size_t)b * L_SZ + src) * E2 + d0 + c];
        }
        sx[r][c] = v;
    }
    __syncthreads();

    const int c  = tid & (CCH - 1);
    const int t0 = tid >> 7;
    const int d  = d0 + c;
    const float* w = dir ? wb : wf;
    const float w0 = w[d * 4 + 0], w1 = w[d * 4 + 1];
    const float w2 = w[d * 4 + 2], w3 = w[d * 4 + 3];
    const float bias = dir ? bb[d] : bf[d];

    #pragma unroll
    for (int t = t0; t < CTOK; t += 2) {
        const float acc = bias + w0 * sx[t][c] + w1 * sx[t + 1][c]
                               + w2 * sx[t + 2][c] + w3 * sx[t + 3][c];
        const size_t o = ((size_t)dir * NTOK + (size_t)b * L_SZ + l0 + t) * D_INNER + d;
        s_xch[o] = __float2half_rn(siluf(acc));
    }
}

// ---------------- Selective scan: smem-staged, 4-way state split ----------------
#define ST  64
#define SCH 64

__global__ __launch_bounds__(256) void scan_kernel(
    const float* __restrict__ A_log_f, const float* __restrict__ D_f,
    const float* __restrict__ A_log_b, const float* __restrict__ D_b)
{
    const int dir = blockIdx.z;
    const int b   = blockIdx.y;
    const int d0  = blockIdx.x * SCH;
    const int tid = threadIdx.x;
    const int ch  = tid >> 2;
    const int sg  = tid & 3;
    const int d   = d0 + ch;

    const size_t dirTok = (size_t)dir * NTOK;
    const __half* xch = s_xch + dirTok * D_INNER;
    const float* dtp  = g_dt   + dirTok * D_INNER;
    const float* xdbl = g_xdbl + dirTok * XDBL_C;
    float*       yout = g_y    + dirTok * D_INNER;
    const float* Alog = dir ? A_log_b : A_log_f;
    const float* Dv   = dir ? D_b     : D_f;

    float A[4];
    #pragma unroll
    for (int j = 0; j < 4; j++) A[j] = -__expf(Alog[d * D_STATE + sg * 4 + j]);
    const float Dd = Dv[d];

    float h[4] = {0.f, 0.f, 0.f, 0.f};

    __shared__ float s_u [ST][SCH];
    __shared__ float s_dt[ST][SCH];
    __shared__ float s_z [ST][SCH];
    __shared__ __align__(16) float s_B[ST][D_STATE];
    __shared__ __align__(16) float s_C[ST][D_STATE];

    for (int l0 = 0; l0 < L_SZ; l0 += ST) {
        __syncthreads();
        #pragma unroll
        for (int i = tid; i < ST * SCH; i += 256) {
            const int t = i >> 6;
            const int c = i & 63;
            const size_t gl = ((size_t)b * L_SZ + l0 + t) * D_INNER + d0 + c;
            s_u[t][c]  = __half2float(xch[gl]);
            s_dt[t][c] = dtp[gl];
            const int lsrc = dir ? (L_SZ - 1 - (l0 + t)) : (l0 + t);
            s_z[t][c]  = g_xz[((size_t)b * L_SZ + lsrc) * E2 + D_INNER + d0 + c];
        }
        #pragma unroll
        for (int i = tid; i < ST * 32; i += 256) {
            const int t = i >> 5;
            const int c = i & 31;
            const float v = xdbl[((size_t)b * L_SZ + l0 + t) * XDBL_C + DT_RANK + c];
            if (c < D_STATE) s_B[t][c] = v;
            else             s_C[t][c - D_STATE] = v;
        }
        __syncthreads();

        for (int t = 0; t < ST; t++) {
            const float u   = s_u[t][ch];
            const float dtv = s_dt[t][ch];
            const float dtu = dtv * u;
            const float4 Bv = *(const float4*)&s_B[t][sg * 4];
            const float4 Cv = *(const float4*)&s_C[t][sg * 4];
            float y;
            {
                const float dA0 = __expf(dtv * A[0]);
                const float dA1 = __expf(dtv * A[1]);
                const float dA2 = __expf(dtv * A[2]);
                const float dA3 = __expf(dtv * A[3]);
                h[0] = h[0] * dA0 + dtu * Bv.x;
                h[1] = h[1] * dA1 + dtu * Bv.y;
                h[2] = h[2] * dA2 + dtu * Bv.z;
                h[3] = h[3] * dA3 + dtu * Bv.w;
                y = h[0] * Cv.x + h[1] * Cv.y + h[2] * Cv.z + h[3] * Cv.w;
            }
            y += __shfl_xor_sync(0xFFFFFFFF, y, 1);
            y += __shfl_xor_sync(0xFFFFFFFF, y, 2);
            if (sg == 0) {
                y += u * Dd;
                const int l = l0 + t;
                const int lsrc = dir ? (L_SZ - 1 - l) : l;
                const float zv = s_z[t][ch];
                yout[((size_t)b * L_SZ + lsrc) * D_INNER + d] = y * siluf(zv);
            }
        }
    }
}

// ---------------- Launch ----------------
extern "C" void kernel_launch(void* const* d_in, const int* in_sizes, int n_in,
                              void* d_out, int out_size)
{
    const float* x            = (const float*)d_in[0];
    const float* in_proj_w    = (const float*)d_in[1];
    const float* out_proj_w   = (const float*)d_in[2];
    const float* conv1d_w     = (const float*)d_in[3];
    const float* conv1d_bias  = (const float*)d_in[4];
    const float* x_proj_w     = (const float*)d_in[5];
    const float* dt_proj_w    = (const float*)d_in[6];
    const float* dt_proj_bias = (const float*)d_in[7];
    const float* A_log        = (const float*)d_in[8];
    const float* Dvec         = (const float*)d_in[9];
    const float* conv1d_w_b   = (const float*)d_in[10];
    const float* conv1d_bias_b= (const float*)d_in[11];
    const float* x_proj_w_b   = (const float*)d_in[12];
    const float* dt_proj_w_b  = (const float*)d_in[13];
    const float* dt_proj_bias_b=(const float*)d_in[14];
    const float* A_log_b      = (const float*)d_in[15];
    const float* D_b          = (const float*)d_in[16];
    float* out = (float*)d_out;

    float *p_xz, *p_dt, *p_xdbl, *p_y;
    __half *p_xh,*p_wi,*p_wo,*p_wx,*p_wd,*p_xch,*p_dtrh,*p_ysh;
    cudaGetSymbolAddress((void**)&p_xz,   g_xz);
    cudaGetSymbolAddress((void**)&p_dt,   g_dt);
    cudaGetSymbolAddress((void**)&p_xdbl, g_xdbl);
    cudaGetSymbolAddress((void**)&p_y,    g_y);
    cudaGetSymbolAddress((void**)&p_xh,  s_xh);
    cudaGetSymbolAddress((void**)&p_wi,  s_wi);
    cudaGetSymbolAddress((void**)&p_wo,  s_wo);
    cudaGetSymbolAddress((void**)&p_wx,  s_wx);
    cudaGetSymbolAddress((void**)&p_wd,  s_wd);
    cudaGetSymbolAddress((void**)&p_xch, s_xch);
    cudaGetSymbolAddress((void**)&p_dtrh,s_dtrh);
    cudaGetSymbolAddress((void**)&p_ysh, s_ysh);

    cudaFuncSetAttribute(gemm_sp<256>, cudaFuncAttributeMaxDynamicSharedMemorySize,
                         NSTAGE * (10240 + 256 * 80));
    cudaFuncSetAttribute(gemm_sp<128>, cudaFuncAttributeMaxDynamicSharedMemorySize,
                         NSTAGE * (10240 + 128 * 80));

    const size_t tokDI = (size_t)NTOK * D_INNER;
    const size_t tokXD = (size_t)NTOK * XDBL_C;
    const size_t wx1   = (size_t)XDBL_C * D_INNER;
    const size_t wd1   = (size_t)D_INNER * DT_RANK;
    const size_t dtr1  = (size_t)NTOK * DT_RANK;

    // 1) all conversions in one launch
    {
        CvtSegs cs;
        cs.src[0] = x;           cs.dst[0] = p_xh;        cs.n4[0] = NTOK * DIM / 4;
        cs.src[1] = in_proj_w;   cs.dst[1] = p_wi;        cs.n4[1] = E2 * DIM / 4;
        cs.src[2] = out_proj_w;  cs.dst[2] = p_wo;        cs.n4[2] = DIM * D_INNER / 4;
        cs.src[3] = x_proj_w;    cs.dst[3] = p_wx;        cs.n4[3] = (int)(wx1 / 4);
        cs.src[4] = x_proj_w_b;  cs.dst[4] = p_wx + wx1;  cs.n4[4] = (int)(wx1 / 4);
        cs.src[5] = dt_proj_w;   cs.dst[5] = p_wd;        cs.n4[5] = (int)(wd1 / 4);
        cs.src[6] = dt_proj_w_b; cs.dst[6] = p_wd + wd1;  cs.n4[6] = (int)(wd1 / 4);
        int total4 = 0;
        for (int i = 0; i < NSEG; i++) total4 += cs.n4[i];
        cvt_all<<<4096, 256>>>(cs, total4);
    }

    // 2) in_proj (16384 x 3072, K=768)
    {
        GArg a{p_xh, p_wi, nullptr, p_xz, nullptr};
        dim3 grid(E2 / 256, NTOK / BM, 1);
        gemm_sp<256><<<grid, 512, NSTAGE*(10240+256*80)>>>(a, a, DIM, DIM, E2, NTOK, E2, DIM, 0);
    }

    // 3) conv + silu -> fp16
    {
        dim3 grid(D_INNER / CCH, L_SZ / CTOK, 2 * B_SZ);
        conv_silu_kernel<<<grid, 256>>>(conv1d_w, conv1d_bias, conv1d_w_b, conv1d_bias_b);
    }

    // 4) x_proj both dirs (16384 x 80, K=1536), BN=128, epilogue splits dt_r
    {
        GArg a0{p_xch,         p_wx,       nullptr, p_xdbl,         p_dtrh};
        GArg a1{p_xch + tokDI, p_wx + wx1, nullptr, p_xdbl + tokXD, p_dtrh + dtr1};
        dim3 grid(1, NTOK / BM, 2);
        gemm_sp<128><<<grid, 512, NSTAGE*(10240+128*80)>>>(a0, a1, D_INNER, D_INNER, XDBL_C, NTOK, XDBL_C, D_INNER, 2);
    }

    // 5) dt_proj both dirs (16384 x 1536, K=48) + softplus
    {
        GArg a0{p_dtrh,        p_wd,       dt_proj_bias,   p_dt,         nullptr};
        GArg a1{p_dtrh + dtr1, p_wd + wd1, dt_proj_bias_b, p_dt + tokDI, nullptr};
        dim3 grid(D_INNER / 256, NTOK / BM, 2);
        gemm_sp<256><<<grid, 512, NSTAGE*(10240+256*80)>>>(a0, a1, DT_RANK, DT_RANK, D_INNER, NTOK, D_INNER, DT_RANK, 1);
    }

    // 6) selective scan  <-- profiled launch (ncu -s 5 -c 1)
    {
        dim3 grid(D_INNER / SCH, B_SZ, 2);
        scan_kernel<<<grid, 256>>>(A_log, Dvec, A_log_b, D_b);
    }

    // 7) ysum = fp16(y_f + y_b)
    cvt_add<<<2048, 256>>>(p_y, p_y + tokDI, p_ysh, (int)(tokDI / 4));

    // 8) out_proj (16384 x 768, K=1536)
    {
        GArg a{p_ysh, p_wo, nullptr, out, nullptr};
        dim3 grid(DIM / 256, NTOK / BM, 1);
        gemm_sp<256><<<grid, 512, NSTAGE*(10240+256*80)>>>(a, a, D_INNER, D_INNER, DIM, NTOK, DIM, D_INNER, 0);
    }
}